// round 7
// baseline (speedup 1.0000x reference)
#include <cuda_runtime.h>

#define NTOK 65536
#define DDIM 512
#define KT 512
#define KE 256
#define KD 512
#define KTOT (KT + KE + KD + KD)

// ---------------- scratch (device globals; no runtime alloc) ----------------
__device__ float g_tfeat[(size_t)NTOK * DDIM];
__device__ float g_efeat[(size_t)NTOK * DDIM];
__device__ float g_dfeat[(size_t)NTOK * DDIM];
__device__ float g_resid[(size_t)NTOK * DDIM];
__device__ float g_rown[4 * NTOK];           // |f|^2 per token per stage
__device__ float g_rpart[12 * NTOK];         // per-colblock partial |f|^2 (3 stages x 4 blocks)
__device__ int   g_idx[4 * NTOK];            // argmin indices per stage
__device__ float g_E[(size_t)KTOT * DDIM];   // projected codebooks Et,Ee,E0,E1
__device__ float g_cn[KTOT];                 // |c|^2 per code
__device__ float g_lacc[4];                  // loss sum accumulators

// ---------------- packed fp32x2 helpers ----------------
#define FMA2(d, a, b) asm("fma.rn.f32x2 %0, %1, %2, %0;" : "+l"(d) : "l"(a), "l"(b))
#define PACK2(d, x, y) asm("mov.b64 %0, {%1, %2};" : "=l"(d) : "f"(x), "f"(y))
#define UNPACK2(x, y, d) asm("mov.b64 {%0, %1}, %2;" : "=f"(x), "=f"(y) : "l"(d))

// ---------------- 128x128x16 tile, 128 threads, 16x8 micro-tile --------------
#define TBM 128
#define TBN 128
#define TBK 16
#define PADW 132
#define STAGE (2 * TBK * PADW)   // As + Bs, one stage (floats)
#define SMEMF (2 * STAGE)        // double buffered

__device__ __forceinline__ void ldg_tile(const float* Ap, const float* Bp,
                                         int lda, int ldb, int ko,
                                         float4 a[4], float4 b[4])
{
    #pragma unroll
    for (int p = 0; p < 4; p++) {
        a[p] = *(const float4*)(Ap + (size_t)(32 * p) * lda + ko);
        b[p] = *(const float4*)(Bp + (size_t)(32 * p) * ldb + ko);
    }
}

__device__ __forceinline__ void sts_tile(float* s, int str, int sto,
                                         const float4 a[4], const float4 b[4])
{
    float* As_ = s;
    float* Bs_ = s + TBK * PADW;
    #pragma unroll
    for (int p = 0; p < 4; p++) {
        int r = str + 32 * p;
        As_[(sto + 0) * PADW + r] = a[p].x;
        As_[(sto + 1) * PADW + r] = a[p].y;
        As_[(sto + 2) * PADW + r] = a[p].z;
        As_[(sto + 3) * PADW + r] = a[p].w;
        Bs_[(sto + 0) * PADW + r] = b[p].x;
        Bs_[(sto + 1) * PADW + r] = b[p].y;
        Bs_[(sto + 2) * PADW + r] = b[p].z;
        Bs_[(sto + 3) * PADW + r] = b[p].w;
    }
}

// acc[ip][j]: row-pair ip (rows tm*16+2ip, +2ip+1) x col j (tn*8+j)
__device__ __forceinline__ void mm_tile(const float* s, int tm, int tn,
                                        unsigned long long acc[8][8])
{
    const float* As_ = s;
    const float* Bs_ = s + TBK * PADW;
    #pragma unroll
    for (int k = 0; k < TBK; k++) {
        const float* ap = &As_[k * PADW + tm * 16];
        const float* bp = &Bs_[k * PADW + tn * 8];
        float4 a0 = *(const float4*)ap;
        float4 a1 = *(const float4*)(ap + 4);
        float4 a2 = *(const float4*)(ap + 8);
        float4 a3 = *(const float4*)(ap + 12);
        float4 b0 = *(const float4*)bp;
        float4 b1 = *(const float4*)(bp + 4);
        unsigned long long ap8[8];
        PACK2(ap8[0], a0.x, a0.y); PACK2(ap8[1], a0.z, a0.w);
        PACK2(ap8[2], a1.x, a1.y); PACK2(ap8[3], a1.z, a1.w);
        PACK2(ap8[4], a2.x, a2.y); PACK2(ap8[5], a2.z, a2.w);
        PACK2(ap8[6], a3.x, a3.y); PACK2(ap8[7], a3.z, a3.w);
        float bv[8] = {b0.x, b0.y, b0.z, b0.w, b1.x, b1.y, b1.z, b1.w};
        #pragma unroll
        for (int j = 0; j < 8; j++) {
            unsigned long long bb;
            PACK2(bb, bv[j], bv[j]);
            #pragma unroll
            for (int i = 0; i < 8; i++)
                FMA2(acc[i][j], ap8[i], bb);
        }
    }
}

// mainloop filling acc; leaves smem free for reuse after final barrier
__device__ __forceinline__ void gemm_mainloop(
    const float* A, int lda, const float* B, int ldb, int Kd,
    int row0, int col0, float* smem, unsigned long long acc[8][8])
{
    int t = threadIdx.x;
    int tm = t >> 4, tn = t & 15;
    int str = t >> 2, sto = (t & 3) * 4;
    const float* Ap = A + (size_t)(row0 + str) * lda + sto;
    const float* Bp = B + (size_t)(col0 + str) * ldb + sto;
    float4 ar[4], br[4];
    ldg_tile(Ap, Bp, lda, ldb, 0, ar, br);
    sts_tile(smem, str, sto, ar, br);
    __syncthreads();
    int nt = Kd / TBK;
    for (int kt = 0; kt < nt; kt++) {
        if (kt + 1 < nt) ldg_tile(Ap, Bp, lda, ldb, (kt + 1) * TBK, ar, br);
        mm_tile(smem + (kt & 1) * STAGE, tm, tn, acc);
        if (kt + 1 < nt) sts_tile(smem + ((kt + 1) & 1) * STAGE, str, sto, ar, br);
        __syncthreads();
    }
    (void)tm; (void)tn;
}

// ---- fused 3 feature linears + per-colblock row sumsq partials --------------
__global__ __launch_bounds__(128, 3) void feat3_gemm(
    const float* __restrict__ x,
    const float* __restrict__ tW, const float* __restrict__ tb,
    const float* __restrict__ eW, const float* __restrict__ eb,
    const float* __restrict__ dW, const float* __restrict__ db,
    float* __restrict__ tf, float* __restrict__ ef, float* __restrict__ df)
{
    __shared__ float smem[SMEMF];
    int z = blockIdx.z;
    const float* W = (z == 0) ? tW : (z == 1) ? eW : dW;
    const float* bias = (z == 0) ? tb : (z == 1) ? eb : db;
    float* C = (z == 0) ? tf : (z == 1) ? ef : df;
    int row0 = blockIdx.y * TBM, col0 = blockIdx.x * TBN;

    unsigned long long acc[8][8] = {};
    gemm_mainloop(x, DDIM, W, DDIM, DDIM, row0, col0, smem, acc);

    int t = threadIdx.x;
    int tm = t >> 4, tn = t & 15;
    float* s_sq = smem;                       // [128][17] alias, safe after final barrier
    #pragma unroll
    for (int ip = 0; ip < 8; ip++) {
        float lo[8], hi[8];
        #pragma unroll
        for (int j = 0; j < 8; j++) UNPACK2(lo[j], hi[j], acc[ip][j]);
        int r0 = row0 + tm * 16 + 2 * ip;
        int c0 = col0 + tn * 8;
        float plo = 0.f, phi = 0.f;
        #pragma unroll
        for (int j = 0; j < 8; j++) {
            float bb = bias[c0 + j];
            lo[j] += bb; hi[j] += bb;
            plo += lo[j] * lo[j];
            phi += hi[j] * hi[j];
        }
        float4 w0 = {lo[0], lo[1], lo[2], lo[3]};
        float4 w1 = {lo[4], lo[5], lo[6], lo[7]};
        float4 w2 = {hi[0], hi[1], hi[2], hi[3]};
        float4 w3 = {hi[4], hi[5], hi[6], hi[7]};
        *(float4*)(C + (size_t)r0 * DDIM + c0) = w0;
        *(float4*)(C + (size_t)r0 * DDIM + c0 + 4) = w1;
        *(float4*)(C + (size_t)(r0 + 1) * DDIM + c0) = w2;
        *(float4*)(C + (size_t)(r0 + 1) * DDIM + c0 + 4) = w3;
        s_sq[(tm * 16 + 2 * ip) * 17 + tn] = plo;
        s_sq[(tm * 16 + 2 * ip + 1) * 17 + tn] = phi;
    }
    __syncthreads();
    if (t < TBM) {
        float s = 0.f;
        #pragma unroll
        for (int c = 0; c < 16; c++) s += s_sq[t * 17 + c];
        g_rpart[(size_t)(z * 4 + blockIdx.x) * NTOK + row0 + t] = s;
    }
}

// deterministic 4-way combine of colblock partials -> g_rown[stage][row]
__global__ void combine_rown()
{
    int i = blockIdx.x * 256 + threadIdx.x;  // i < 3*NTOK
    int z = i / NTOK, r = i - z * NTOK;
    const float* p = g_rpart + (size_t)(z * 4) * NTOK + r;
    float s = ((p[0] + p[(size_t)NTOK]) + p[(size_t)2 * NTOK]) + p[(size_t)3 * NTOK];
    g_rown[z * NTOK + r] = s;
}

// ---- fused E-projection: E = cb @ oW_slice^T (4 small GEMMs, one launch) ----
__global__ __launch_bounds__(128, 3) void eproj_gemm(
    const float* __restrict__ tcb, const float* __restrict__ ecb,
    const float* __restrict__ cb0, const float* __restrict__ cb1,
    const float* __restrict__ oW, float* __restrict__ E)
{
    __shared__ float smem[SMEMF];
    int y = blockIdx.y;
    const float* A;
    int boff, rb;
    size_t coff;
    if (y < 4)       { A = tcb; boff = 0;        coff = 0;            rb = y; }
    else if (y < 6)  { A = ecb; boff = DDIM;     coff = KT;           rb = y - 4; }
    else if (y < 10) { A = cb0; boff = 2 * DDIM; coff = KT + KE;      rb = y - 6; }
    else             { A = cb1; boff = 2 * DDIM; coff = KT + KE + KD; rb = y - 10; }
    int row0 = rb * TBM, col0 = blockIdx.x * TBN;

    unsigned long long acc[8][8] = {};
    gemm_mainloop(A, DDIM, oW + boff, 3 * DDIM, DDIM, row0, col0, smem, acc);

    int t = threadIdx.x;
    int tm = t >> 4, tn = t & 15;
    float* C = E + coff * DDIM;
    #pragma unroll
    for (int ip = 0; ip < 8; ip++) {
        float lo[8], hi[8];
        #pragma unroll
        for (int j = 0; j < 8; j++) UNPACK2(lo[j], hi[j], acc[ip][j]);
        int r0 = row0 + tm * 16 + 2 * ip;
        int c0 = col0 + tn * 8;
        float4 w0 = {lo[0], lo[1], lo[2], lo[3]};
        float4 w1 = {lo[4], lo[5], lo[6], lo[7]};
        float4 w2 = {hi[0], hi[1], hi[2], hi[3]};
        float4 w3 = {hi[4], hi[5], hi[6], hi[7]};
        *(float4*)(C + (size_t)r0 * DDIM + c0) = w0;
        *(float4*)(C + (size_t)r0 * DDIM + c0 + 4) = w1;
        *(float4*)(C + (size_t)(r0 + 1) * DDIM + c0) = w2;
        *(float4*)(C + (size_t)(r0 + 1) * DDIM + c0 + 4) = w3;
    }
}

// ---------------- fused distance GEMM + rowwise argmin ----------------
__device__ __forceinline__ void vq_block(
    const float* feat, const float* cb, const float* rown_,
    const float* cnorm, int Kcodes,
    int* idx_out, float* idxf_out, int row0, float* smem)
{
    int t = threadIdx.x;
    int tm = t >> 4, tn = t & 15;

    float bestv[16];
    int bidx[16];
    #pragma unroll
    for (int i = 0; i < 16; i++) { bestv[i] = 3.4e38f; bidx[i] = 0; }

    for (int nc = 0; nc < Kcodes; nc += TBN) {
        unsigned long long acc[8][8] = {};
        gemm_mainloop(feat, DDIM, cb + (size_t)nc * DDIM, DDIM, DDIM,
                      row0, 0, smem, acc);
        float cw[8];
        #pragma unroll
        for (int j = 0; j < 8; j++) cw[j] = cnorm[nc + tn * 8 + j];
        #pragma unroll
        for (int ip = 0; ip < 8; ip++) {
            float lo[8], hi[8];
            #pragma unroll
            for (int j = 0; j < 8; j++) UNPACK2(lo[j], hi[j], acc[ip][j]);
            float An0 = rown_[row0 + tm * 16 + 2 * ip];
            float An1 = rown_[row0 + tm * 16 + 2 * ip + 1];
            #pragma unroll
            for (int j = 0; j < 8; j++) {
                int code = nc + tn * 8 + j;
                float d0 = (An0 + cw[j]) - 2.0f * lo[j];
                if (d0 < bestv[2 * ip]) { bestv[2 * ip] = d0; bidx[2 * ip] = code; }
                float d1 = (An1 + cw[j]) - 2.0f * hi[j];
                if (d1 < bestv[2 * ip + 1]) { bestv[2 * ip + 1] = d1; bidx[2 * ip + 1] = code; }
            }
        }
        __syncthreads();   // protect smem reuse across nc iterations
    }

    // cross-thread reduce (alias smem)
    float* sval = smem;                 // [128][16]
    int*   sidx = (int*)(smem + 2048);  // [128][16]
    #pragma unroll
    for (int i = 0; i < 16; i++) {
        sval[(tm * 16 + i) * 16 + tn] = bestv[i];
        sidx[(tm * 16 + i) * 16 + tn] = bidx[i];
    }
    __syncthreads();
    if (t < TBM) {
        float bv = 3.4e38f;
        int bi = 0x7fffffff;
        #pragma unroll
        for (int c = 0; c < 16; c++) {
            float v = sval[t * 16 + c];
            int id = sidx[t * 16 + c];
            if (v < bv || (v == bv && id < bi)) { bv = v; bi = id; }
        }
        idx_out[row0 + t] = bi;
        idxf_out[row0 + t] = (float)bi;
    }
}

// fused first-3 VQ stages (y selects stage)
__global__ __launch_bounds__(128, 3) void vq3(
    const float* __restrict__ tf, const float* __restrict__ ef,
    const float* __restrict__ df,
    const float* __restrict__ tcb, const float* __restrict__ ecb,
    const float* __restrict__ cb0,
    const float* __restrict__ rown_, const float* __restrict__ cn_,
    int* __restrict__ idx_, float* __restrict__ idxf_)
{
    __shared__ float smem[SMEMF];
    int s = blockIdx.y;
    const float* feat = (s == 0) ? tf : (s == 1) ? ef : df;
    const float* cb   = (s == 0) ? tcb : (s == 1) ? ecb : cb0;
    const float* rn   = rown_ + s * NTOK;
    const float* cn   = (s == 0) ? cn_ : (s == 1) ? (cn_ + KT) : (cn_ + KT + KE);
    int Kc            = (s == 1) ? KE : KT;
    vq_block(feat, cb, rn, cn, Kc, idx_ + s * NTOK, idxf_ + s * NTOK,
             blockIdx.x * TBM, smem);
}

__global__ __launch_bounds__(128, 3) void vq1(
    const float* __restrict__ feat, const float* __restrict__ cb,
    const float* __restrict__ rown_, const float* __restrict__ cnorm,
    int Kcodes, int* __restrict__ idx_out, float* __restrict__ idxf_out)
{
    __shared__ float smem[SMEMF];
    vq_block(feat, cb, rown_, cnorm, Kcodes, idx_out, idxf_out,
             blockIdx.x * TBM, smem);
}

// ---------------- helpers ----------------
__device__ __forceinline__ float blockReduceSum128(float v)
{
    __shared__ float sm[128];
    int t = threadIdx.x;
    sm[t] = v;
    __syncthreads();
    for (int s = 64; s > 0; s >>= 1) {
        if (t < s) sm[t] += sm[t + s];
        __syncthreads();
    }
    float r = sm[0];
    __syncthreads();
    return r;
}

// all 4 codebook norms in one launch (same per-row math as before)
__global__ __launch_bounds__(128) void cbnorm(
    const float* __restrict__ tcb, const float* __restrict__ ecb,
    const float* __restrict__ cb0, const float* __restrict__ cb1,
    float* __restrict__ out)
{
    int row = blockIdx.x;
    const float* src;
    if (row < KT)                src = tcb + (size_t)row * DDIM;
    else if (row < KT + KE)      src = ecb + (size_t)(row - KT) * DDIM;
    else if (row < KT + KE + KD) src = cb0 + (size_t)(row - KT - KE) * DDIM;
    else                         src = cb1 + (size_t)(row - KT - KE - KD) * DDIM;
    int t = threadIdx.x;
    float4 v = ((const float4*)src)[t];
    float s = v.x * v.x + v.y * v.y + v.z * v.z + v.w * v.w;
    float tot = blockReduceSum128(s);
    if (t == 0) out[row] = tot;
}

__global__ __launch_bounds__(128) void resid_loss(
    const float* __restrict__ tf, const float* __restrict__ ef,
    const float* __restrict__ df,
    const float* __restrict__ tcb, const float* __restrict__ ecb,
    const float* __restrict__ cb0,
    const int* __restrict__ idx,
    float* __restrict__ resid, float* __restrict__ rownR,
    float* __restrict__ lacc)
{
    int n = blockIdx.x;
    int t = threadIdx.x;
    int it = idx[0 * NTOK + n];
    int ie = idx[1 * NTOK + n];
    int i0 = idx[2 * NTOK + n];

    float4 a, c;
    a = ((const float4*)(tf + (size_t)n * DDIM))[t];
    c = ((const float4*)(tcb + (size_t)it * DDIM))[t];
    float dx = c.x - a.x, dy = c.y - a.y, dz = c.z - a.z, dw = c.w - a.w;
    float st = dx * dx + dy * dy + dz * dz + dw * dw;

    a = ((const float4*)(ef + (size_t)n * DDIM))[t];
    c = ((const float4*)(ecb + (size_t)ie * DDIM))[t];
    dx = c.x - a.x; dy = c.y - a.y; dz = c.z - a.z; dw = c.w - a.w;
    float se = dx * dx + dy * dy + dz * dz + dw * dw;

    a = ((const float4*)(df + (size_t)n * DDIM))[t];
    c = ((const float4*)(cb0 + (size_t)i0 * DDIM))[t];
    float4 r;
    r.x = a.x - c.x; r.y = a.y - c.y; r.z = a.z - c.z; r.w = a.w - c.w;
    ((float4*)(resid + (size_t)n * DDIM))[t] = r;
    float sr = r.x * r.x + r.y * r.y + r.z * r.z + r.w * r.w;

    float tt = blockReduceSum128(st);
    if (t == 0) atomicAdd(&lacc[0], tt);
    float te = blockReduceSum128(se);
    if (t == 0) atomicAdd(&lacc[1], te);
    float tr = blockReduceSum128(sr);
    if (t == 0) { atomicAdd(&lacc[2], tr); rownR[n] = tr; }
}

__global__ __launch_bounds__(128) void finalize_out(
    const float* __restrict__ E,
    const float* __restrict__ outb,
    const float* __restrict__ cb1,
    const float* __restrict__ resid,
    const int* __restrict__ idx,
    float* __restrict__ qout,
    float* __restrict__ lacc)
{
    int n = blockIdx.x;
    int t = threadIdx.x;
    int it = idx[0 * NTOK + n];
    int ie = idx[1 * NTOK + n];
    int i0 = idx[2 * NTOK + n];
    int i1 = idx[3 * NTOK + n];

    const float4* Et = (const float4*)(E + (size_t)it * DDIM);
    const float4* Ee = (const float4*)(E + (size_t)(KT + ie) * DDIM);
    const float4* E0 = (const float4*)(E + (size_t)(KT + KE + i0) * DDIM);
    const float4* E1 = (const float4*)(E + (size_t)(KT + KE + KD + i1) * DDIM);
    const float4* Bb = (const float4*)outb;

    float4 q;
    float4 v0 = Et[t], v1 = Ee[t], v2 = E0[t], v3 = E1[t], vb = Bb[t];
    q.x = v0.x + v1.x + v2.x + v3.x + vb.x;
    q.y = v0.y + v1.y + v2.y + v3.y + vb.y;
    q.z = v0.z + v1.z + v2.z + v3.z + vb.z;
    q.w = v0.w + v1.w + v2.w + v3.w + vb.w;
    ((float4*)(qout + (size_t)n * DDIM))[t] = q;

    float4 c = ((const float4*)(cb1 + (size_t)i1 * DDIM))[t];
    float4 r = ((const float4*)(resid + (size_t)n * DDIM))[t];
    float dx = c.x - r.x, dy = c.y - r.y, dz = c.z - r.z, dw = c.w - r.w;
    float s1 = dx * dx + dy * dy + dz * dz + dw * dw;
    float ts = blockReduceSum128(s1);
    if (t == 0) atomicAdd(&lacc[3], ts);
}

__global__ void zero_lacc(float* lacc)
{
    if (threadIdx.x < 4) lacc[threadIdx.x] = 0.f;
}

__global__ void write_loss(const float* __restrict__ lacc, float* __restrict__ out)
{
    if (threadIdx.x == 0) {
        float total = lacc[0] + lacc[1] + lacc[2] + lacc[3];
        out[0] = 1.25f * total * (1.0f / ((float)NTOK * (float)DDIM));
    }
}

// ---------------- host ----------------
extern "C" void kernel_launch(void* const* d_in, const int* in_sizes, int n_in,
                              void* d_out, int out_size)
{
    const float* x   = (const float*)d_in[0];
    const float* tW  = (const float*)d_in[1];
    const float* tb  = (const float*)d_in[2];
    const float* eW  = (const float*)d_in[3];
    const float* eb  = (const float*)d_in[4];
    const float* dW  = (const float*)d_in[5];
    const float* db  = (const float*)d_in[6];
    const float* oW  = (const float*)d_in[7];
    const float* ob  = (const float*)d_in[8];
    const float* tcb = (const float*)d_in[9];
    const float* ecb = (const float*)d_in[10];
    const float* cb0 = (const float*)d_in[11];
    const float* cb1 = (const float*)d_in[12];

    float* out = (float*)d_out;
    float* q_out    = out;                               // [NTOK*DDIM]
    float* idxf     = out + (size_t)NTOK * DDIM;         // 4x [NTOK]
    float* loss_out = idxf + (size_t)4 * NTOK;           // [1]

    float *tfeat, *efeat, *dfeat, *resid, *rown, *E, *cn, *lacc;
    int* idx;
    cudaGetSymbolAddress((void**)&tfeat, g_tfeat);
    cudaGetSymbolAddress((void**)&efeat, g_efeat);
    cudaGetSymbolAddress((void**)&dfeat, g_dfeat);
    cudaGetSymbolAddress((void**)&resid, g_resid);
    cudaGetSymbolAddress((void**)&rown,  g_rown);
    cudaGetSymbolAddress((void**)&idx,   g_idx);
    cudaGetSymbolAddress((void**)&E,     g_E);
    cudaGetSymbolAddress((void**)&cn,    g_cn);
    cudaGetSymbolAddress((void**)&lacc,  g_lacc);

    zero_lacc<<<1, 32>>>(lacc);

    // 3 feature linears (+ fused rownorm partials) in one launch
    dim3 gfeat(DDIM / TBN, NTOK / TBM, 3);
    feat3_gemm<<<gfeat, 128>>>(x, tW, tb, eW, eb, dW, db, tfeat, efeat, dfeat);

    // combine rownorm partials (deterministic order)
    combine_rown<<<3 * NTOK / 256, 256>>>();

    // all codebook norms, one launch
    cbnorm<<<KTOT, 128>>>(tcb, ecb, cb0, cb1, cn);

    // projected codebooks, one fused launch: E = cb @ oW_slice^T
    eproj_gemm<<<dim3(DDIM / TBN, 14), 128>>>(tcb, ecb, cb0, cb1, oW, E);

    // first 3 VQ stages fused
    dim3 gvq(NTOK / TBM, 3);
    vq3<<<gvq, 128>>>(tfeat, efeat, dfeat, tcb, ecb, cb0, rown, cn, idx, idxf);

    // residual + losses for first three quantizers
    resid_loss<<<NTOK, 128>>>(tfeat, efeat, dfeat, tcb, ecb, cb0, idx,
                              resid, rown + 3 * NTOK, lacc);

    // second detail stage on residual
    vq1<<<NTOK / TBM, 128>>>(resid, cb1, rown + 3 * NTOK,
                             cn + KT + KE + KD, KD,
                             idx + 3 * NTOK, idxf + 3 * NTOK);

    // gather-add projected codebooks -> quantized output; stage-1 loss
    finalize_out<<<NTOK, 128>>>(E, ob, cb1, resid, idx, q_out, lacc);

    write_loss<<<1, 32>>>(lacc, loss_out);
}

// round 9
// speedup vs baseline: 1.4954x; 1.4954x over previous
#include <cuda_runtime.h>

#define NTOK 65536
#define DDIM 512
#define KT 512
#define KE 256
#define KD 512
#define KTOT (KT + KE + KD + KD)

// ---------------- scratch (device globals; no runtime alloc) ----------------
__device__ float g_tfeat[(size_t)NTOK * DDIM];
__device__ float g_efeat[(size_t)NTOK * DDIM];
__device__ float g_dfeat[(size_t)NTOK * DDIM];
__device__ float g_resid[(size_t)NTOK * DDIM];
__device__ float g_rown[4 * NTOK];           // |f|^2 per token per stage
__device__ float g_rpart[12 * NTOK];         // per-colblock partial |f|^2 (3 stages x 4 blocks)
__device__ int   g_idx[4 * NTOK];            // argmin indices per stage
__device__ float g_E[(size_t)KTOT * DDIM];   // projected codebooks Et,Ee,E0,E1
__device__ float g_cn[KTOT];                 // |c|^2 per code
__device__ float g_lacc[4];                  // loss sum accumulators

// ---------------- packed fp32x2 helpers ----------------
#define FMA2(d, a, b) asm("fma.rn.f32x2 %0, %1, %2, %0;" : "+l"(d) : "l"(a), "l"(b))
#define PACK2(d, x, y) asm("mov.b64 %0, {%1, %2};" : "=l"(d) : "f"(x), "f"(y))
#define UNPACK2(x, y, d) asm("mov.b64 {%0, %1}, %2;" : "=f"(x), "=f"(y) : "l"(d))

// ---------------- 128x128x16 tile, 128 threads, 16x8 micro-tile --------------
#define TBM 128
#define TBN 128
#define TBK 16
#define PADW 132
#define STAGE (2 * TBK * PADW)   // As + Bs, one stage (floats)
#define SMEMF (2 * STAGE)        // double buffered

__device__ __forceinline__ void ldg_tile(const float* Ap, const float* Bp,
                                         int lda, int ldb, int ko,
                                         float4 a[4], float4 b[4])
{
    #pragma unroll
    for (int p = 0; p < 4; p++) {
        a[p] = *(const float4*)(Ap + (size_t)(32 * p) * lda + ko);
        b[p] = *(const float4*)(Bp + (size_t)(32 * p) * ldb + ko);
    }
}

__device__ __forceinline__ void sts_tile(float* s, int str, int sto,
                                         const float4 a[4], const float4 b[4])
{
    float* As_ = s;
    float* Bs_ = s + TBK * PADW;
    #pragma unroll
    for (int p = 0; p < 4; p++) {
        int r = str + 32 * p;
        As_[(sto + 0) * PADW + r] = a[p].x;
        As_[(sto + 1) * PADW + r] = a[p].y;
        As_[(sto + 2) * PADW + r] = a[p].z;
        As_[(sto + 3) * PADW + r] = a[p].w;
        Bs_[(sto + 0) * PADW + r] = b[p].x;
        Bs_[(sto + 1) * PADW + r] = b[p].y;
        Bs_[(sto + 2) * PADW + r] = b[p].z;
        Bs_[(sto + 3) * PADW + r] = b[p].w;
    }
}

// acc[ip][j]: row-pair ip (rows tm*16+2ip, +2ip+1) x col j (tn*8+j)
__device__ __forceinline__ void mm_tile(const float* s, int tm, int tn,
                                        unsigned long long acc[8][8])
{
    const float* As_ = s;
    const float* Bs_ = s + TBK * PADW;
    #pragma unroll
    for (int k = 0; k < TBK; k++) {
        const float* ap = &As_[k * PADW + tm * 16];
        const float* bp = &Bs_[k * PADW + tn * 8];
        float4 a0 = *(const float4*)ap;
        float4 a1 = *(const float4*)(ap + 4);
        float4 a2 = *(const float4*)(ap + 8);
        float4 a3 = *(const float4*)(ap + 12);
        float4 b0 = *(const float4*)bp;
        float4 b1 = *(const float4*)(bp + 4);
        unsigned long long ap8[8];
        PACK2(ap8[0], a0.x, a0.y); PACK2(ap8[1], a0.z, a0.w);
        PACK2(ap8[2], a1.x, a1.y); PACK2(ap8[3], a1.z, a1.w);
        PACK2(ap8[4], a2.x, a2.y); PACK2(ap8[5], a2.z, a2.w);
        PACK2(ap8[6], a3.x, a3.y); PACK2(ap8[7], a3.z, a3.w);
        float bv[8] = {b0.x, b0.y, b0.z, b0.w, b1.x, b1.y, b1.z, b1.w};
        #pragma unroll
        for (int j = 0; j < 8; j++) {
            unsigned long long bb;
            PACK2(bb, bv[j], bv[j]);
            #pragma unroll
            for (int i = 0; i < 8; i++)
                FMA2(acc[i][j], ap8[i], bb);
        }
    }
}

// mainloop filling acc; leaves smem free for reuse after final barrier
__device__ __forceinline__ void gemm_mainloop(
    const float* A, int lda, const float* B, int ldb, int Kd,
    int row0, int col0, float* smem, unsigned long long acc[8][8])
{
    int t = threadIdx.x;
    int str = t >> 2, sto = (t & 3) * 4;
    int tm = t >> 4, tn = t & 15;
    const float* Ap = A + (size_t)(row0 + str) * lda + sto;
    const float* Bp = B + (size_t)(col0 + str) * ldb + sto;
    float4 ar[4], br[4];
    ldg_tile(Ap, Bp, lda, ldb, 0, ar, br);
    sts_tile(smem, str, sto, ar, br);
    __syncthreads();
    int nt = Kd / TBK;
    for (int kt = 0; kt < nt; kt++) {
        if (kt + 1 < nt) ldg_tile(Ap, Bp, lda, ldb, (kt + 1) * TBK, ar, br);
        mm_tile(smem + (kt & 1) * STAGE, tm, tn, acc);
        if (kt + 1 < nt) sts_tile(smem + ((kt + 1) & 1) * STAGE, str, sto, ar, br);
        __syncthreads();
    }
}

// ---- fused 3 feature linears + per-colblock row sumsq partials --------------
__global__ __launch_bounds__(128, 2) void feat3_gemm(
    const float* __restrict__ x,
    const float* __restrict__ tW, const float* __restrict__ tb,
    const float* __restrict__ eW, const float* __restrict__ eb,
    const float* __restrict__ dW, const float* __restrict__ db,
    float* __restrict__ tf, float* __restrict__ ef, float* __restrict__ df)
{
    __shared__ float smem[SMEMF];
    int z = blockIdx.z;
    const float* W = (z == 0) ? tW : (z == 1) ? eW : dW;
    const float* bias = (z == 0) ? tb : (z == 1) ? eb : db;
    float* C = (z == 0) ? tf : (z == 1) ? ef : df;
    int row0 = blockIdx.y * TBM, col0 = blockIdx.x * TBN;

    unsigned long long acc[8][8] = {};
    gemm_mainloop(x, DDIM, W, DDIM, DDIM, row0, col0, smem, acc);

    int t = threadIdx.x;
    int tm = t >> 4, tn = t & 15;
    float* s_sq = smem;                       // [128][17] alias, safe after final barrier
    #pragma unroll
    for (int ip = 0; ip < 8; ip++) {
        float lo[8], hi[8];
        #pragma unroll
        for (int j = 0; j < 8; j++) UNPACK2(lo[j], hi[j], acc[ip][j]);
        int r0 = row0 + tm * 16 + 2 * ip;
        int c0 = col0 + tn * 8;
        float plo = 0.f, phi = 0.f;
        #pragma unroll
        for (int j = 0; j < 8; j++) {
            float bb = bias[c0 + j];
            lo[j] += bb; hi[j] += bb;
            plo += lo[j] * lo[j];
            phi += hi[j] * hi[j];
        }
        float4 w0 = {lo[0], lo[1], lo[2], lo[3]};
        float4 w1 = {lo[4], lo[5], lo[6], lo[7]};
        float4 w2 = {hi[0], hi[1], hi[2], hi[3]};
        float4 w3 = {hi[4], hi[5], hi[6], hi[7]};
        *(float4*)(C + (size_t)r0 * DDIM + c0) = w0;
        *(float4*)(C + (size_t)r0 * DDIM + c0 + 4) = w1;
        *(float4*)(C + (size_t)(r0 + 1) * DDIM + c0) = w2;
        *(float4*)(C + (size_t)(r0 + 1) * DDIM + c0 + 4) = w3;
        s_sq[(tm * 16 + 2 * ip) * 17 + tn] = plo;
        s_sq[(tm * 16 + 2 * ip + 1) * 17 + tn] = phi;
    }
    __syncthreads();
    if (t < TBM) {
        float s = 0.f;
        #pragma unroll
        for (int c = 0; c < 16; c++) s += s_sq[t * 17 + c];
        g_rpart[(size_t)(z * 4 + blockIdx.x) * NTOK + row0 + t] = s;
    }
}

// deterministic 4-way combine of colblock partials -> g_rown[stage][row]
__global__ void combine_rown()
{
    int i = blockIdx.x * 256 + threadIdx.x;  // i < 3*NTOK
    int z = i / NTOK, r = i - z * NTOK;
    const float* p = g_rpart + (size_t)(z * 4) * NTOK + r;
    float s = ((p[0] + p[(size_t)NTOK]) + p[(size_t)2 * NTOK]) + p[(size_t)3 * NTOK];
    g_rown[z * NTOK + r] = s;
}

// ---- fused E-projection: E = cb @ oW_slice^T (4 small GEMMs, one launch) ----
__global__ __launch_bounds__(128, 2) void eproj_gemm(
    const float* __restrict__ tcb, const float* __restrict__ ecb,
    const float* __restrict__ cb0, const float* __restrict__ cb1,
    const float* __restrict__ oW, float* __restrict__ E)
{
    __shared__ float smem[SMEMF];
    int y = blockIdx.y;
    const float* A;
    int boff, rb;
    size_t coff;
    if (y < 4)       { A = tcb; boff = 0;        coff = 0;            rb = y; }
    else if (y < 6)  { A = ecb; boff = DDIM;     coff = KT;           rb = y - 4; }
    else if (y < 10) { A = cb0; boff = 2 * DDIM; coff = KT + KE;      rb = y - 6; }
    else             { A = cb1; boff = 2 * DDIM; coff = KT + KE + KD; rb = y - 10; }
    int row0 = rb * TBM, col0 = blockIdx.x * TBN;

    unsigned long long acc[8][8] = {};
    gemm_mainloop(A, DDIM, oW + boff, 3 * DDIM, DDIM, row0, col0, smem, acc);

    int t = threadIdx.x;
    int tm = t >> 4, tn = t & 15;
    float* C = E + coff * DDIM;
    #pragma unroll
    for (int ip = 0; ip < 8; ip++) {
        float lo[8], hi[8];
        #pragma unroll
        for (int j = 0; j < 8; j++) UNPACK2(lo[j], hi[j], acc[ip][j]);
        int r0 = row0 + tm * 16 + 2 * ip;
        int c0 = col0 + tn * 8;
        float4 w0 = {lo[0], lo[1], lo[2], lo[3]};
        float4 w1 = {lo[4], lo[5], lo[6], lo[7]};
        float4 w2 = {hi[0], hi[1], hi[2], hi[3]};
        float4 w3 = {hi[4], hi[5], hi[6], hi[7]};
        *(float4*)(C + (size_t)r0 * DDIM + c0) = w0;
        *(float4*)(C + (size_t)r0 * DDIM + c0 + 4) = w1;
        *(float4*)(C + (size_t)(r0 + 1) * DDIM + c0) = w2;
        *(float4*)(C + (size_t)(r0 + 1) * DDIM + c0 + 4) = w3;
    }
}

// ---------------- fused distance GEMM + rowwise argmin ----------------
__device__ __forceinline__ void vq_block(
    const float* feat, const float* cb, const float* rown_,
    const float* cnorm, int Kcodes,
    int* idx_out, float* idxf_out, int row0, float* smem)
{
    int t = threadIdx.x;
    int tm = t >> 4, tn = t & 15;

    float bestv[16];
    int bidx[16];
    #pragma unroll
    for (int i = 0; i < 16; i++) { bestv[i] = 3.4e38f; bidx[i] = 0; }

    for (int nc = 0; nc < Kcodes; nc += TBN) {
        unsigned long long acc[8][8] = {};
        gemm_mainloop(feat, DDIM, cb + (size_t)nc * DDIM, DDIM, DDIM,
                      row0, 0, smem, acc);
        float cw[8];
        #pragma unroll
        for (int j = 0; j < 8; j++) cw[j] = cnorm[nc + tn * 8 + j];
        #pragma unroll
        for (int ip = 0; ip < 8; ip++) {
            float lo[8], hi[8];
            #pragma unroll
            for (int j = 0; j < 8; j++) UNPACK2(lo[j], hi[j], acc[ip][j]);
            float An0 = rown_[row0 + tm * 16 + 2 * ip];
            float An1 = rown_[row0 + tm * 16 + 2 * ip + 1];
            #pragma unroll
            for (int j = 0; j < 8; j++) {
                int code = nc + tn * 8 + j;
                float d0 = (An0 + cw[j]) - 2.0f * lo[j];
                if (d0 < bestv[2 * ip]) { bestv[2 * ip] = d0; bidx[2 * ip] = code; }
                float d1 = (An1 + cw[j]) - 2.0f * hi[j];
                if (d1 < bestv[2 * ip + 1]) { bestv[2 * ip + 1] = d1; bidx[2 * ip + 1] = code; }
            }
        }
        __syncthreads();   // protect smem reuse across nc iterations
    }

    // cross-thread reduce (alias smem)
    float* sval = smem;                 // [128][16]
    int*   sidx = (int*)(smem + 2048);  // [128][16]
    #pragma unroll
    for (int i = 0; i < 16; i++) {
        sval[(tm * 16 + i) * 16 + tn] = bestv[i];
        sidx[(tm * 16 + i) * 16 + tn] = bidx[i];
    }
    __syncthreads();
    if (t < TBM) {
        float bv = 3.4e38f;
        int bi = 0x7fffffff;
        #pragma unroll
        for (int c = 0; c < 16; c++) {
            float v = sval[t * 16 + c];
            int id = sidx[t * 16 + c];
            if (v < bv || (v == bv && id < bi)) { bv = v; bi = id; }
        }
        idx_out[row0 + t] = bi;
        idxf_out[row0 + t] = (float)bi;
    }
}

// fused first-3 VQ stages (y selects stage)
__global__ __launch_bounds__(128, 2) void vq3(
    const float* __restrict__ tf, const float* __restrict__ ef,
    const float* __restrict__ df,
    const float* __restrict__ tcb, const float* __restrict__ ecb,
    const float* __restrict__ cb0,
    const float* __restrict__ rown_, const float* __restrict__ cn_,
    int* __restrict__ idx_, float* __restrict__ idxf_)
{
    __shared__ float smem[SMEMF];
    int s = blockIdx.y;
    const float* feat = (s == 0) ? tf : (s == 1) ? ef : df;
    const float* cb   = (s == 0) ? tcb : (s == 1) ? ecb : cb0;
    const float* rn   = rown_ + s * NTOK;
    const float* cn   = (s == 0) ? cn_ : (s == 1) ? (cn_ + KT) : (cn_ + KT + KE);
    int Kc            = (s == 1) ? KE : KT;
    vq_block(feat, cb, rn, cn, Kc, idx_ + s * NTOK, idxf_ + s * NTOK,
             blockIdx.x * TBM, smem);
}

__global__ __launch_bounds__(128, 2) void vq1(
    const float* __restrict__ feat, const float* __restrict__ cb,
    const float* __restrict__ rown_, const float* __restrict__ cnorm,
    int Kcodes, int* __restrict__ idx_out, float* __restrict__ idxf_out)
{
    __shared__ float smem[SMEMF];
    vq_block(feat, cb, rown_, cnorm, Kcodes, idx_out, idxf_out,
             blockIdx.x * TBM, smem);
}

// ---------------- helpers ----------------
__device__ __forceinline__ float blockReduceSum128(float v)
{
    __shared__ float sm[128];
    int t = threadIdx.x;
    sm[t] = v;
    __syncthreads();
    for (int s = 64; s > 0; s >>= 1) {
        if (t < s) sm[t] += sm[t + s];
        __syncthreads();
    }
    float r = sm[0];
    __syncthreads();
    return r;
}

// all 4 codebook norms in one launch
__global__ __launch_bounds__(128) void cbnorm(
    const float* __restrict__ tcb, const float* __restrict__ ecb,
    const float* __restrict__ cb0, const float* __restrict__ cb1,
    float* __restrict__ out)
{
    int row = blockIdx.x;
    const float* src;
    if (row < KT)                src = tcb + (size_t)row * DDIM;
    else if (row < KT + KE)      src = ecb + (size_t)(row - KT) * DDIM;
    else if (row < KT + KE + KD) src = cb0 + (size_t)(row - KT - KE) * DDIM;
    else                         src = cb1 + (size_t)(row - KT - KE - KD) * DDIM;
    int t = threadIdx.x;
    float4 v = ((const float4*)src)[t];
    float s = v.x * v.x + v.y * v.y + v.z * v.z + v.w * v.w;
    float tot = blockReduceSum128(s);
    if (t == 0) out[row] = tot;
}

__global__ __launch_bounds__(128) void resid_loss(
    const float* __restrict__ tf, const float* __restrict__ ef,
    const float* __restrict__ df,
    const float* __restrict__ tcb, const float* __restrict__ ecb,
    const float* __restrict__ cb0,
    const int* __restrict__ idx,
    float* __restrict__ resid, float* __restrict__ rownR,
    float* __restrict__ lacc)
{
    int n = blockIdx.x;
    int t = threadIdx.x;
    int it = idx[0 * NTOK + n];
    int ie = idx[1 * NTOK + n];
    int i0 = idx[2 * NTOK + n];

    float4 a, c;
    a = ((const float4*)(tf + (size_t)n * DDIM))[t];
    c = ((const float4*)(tcb + (size_t)it * DDIM))[t];
    float dx = c.x - a.x, dy = c.y - a.y, dz = c.z - a.z, dw = c.w - a.w;
    float st = dx * dx + dy * dy + dz * dz + dw * dw;

    a = ((const float4*)(ef + (size_t)n * DDIM))[t];
    c = ((const float4*)(ecb + (size_t)ie * DDIM))[t];
    dx = c.x - a.x; dy = c.y - a.y; dz = c.z - a.z; dw = c.w - a.w;
    float se = dx * dx + dy * dy + dz * dz + dw * dw;

    a = ((const float4*)(df + (size_t)n * DDIM))[t];
    c = ((const float4*)(cb0 + (size_t)i0 * DDIM))[t];
    float4 r;
    r.x = a.x - c.x; r.y = a.y - c.y; r.z = a.z - c.z; r.w = a.w - c.w;
    ((float4*)(resid + (size_t)n * DDIM))[t] = r;
    float sr = r.x * r.x + r.y * r.y + r.z * r.z + r.w * r.w;

    float tt = blockReduceSum128(st);
    if (t == 0) atomicAdd(&lacc[0], tt);
    float te = blockReduceSum128(se);
    if (t == 0) atomicAdd(&lacc[1], te);
    float tr = blockReduceSum128(sr);
    if (t == 0) { atomicAdd(&lacc[2], tr); rownR[n] = tr; }
}

__global__ __launch_bounds__(128) void finalize_out(
    const float* __restrict__ E,
    const float* __restrict__ outb,
    const float* __restrict__ cb1,
    const float* __restrict__ resid,
    const int* __restrict__ idx,
    float* __restrict__ qout,
    float* __restrict__ lacc)
{
    int n = blockIdx.x;
    int t = threadIdx.x;
    int it = idx[0 * NTOK + n];
    int ie = idx[1 * NTOK + n];
    int i0 = idx[2 * NTOK + n];
    int i1 = idx[3 * NTOK + n];

    const float4* Et = (const float4*)(E + (size_t)it * DDIM);
    const float4* Ee = (const float4*)(E + (size_t)(KT + ie) * DDIM);
    const float4* E0 = (const float4*)(E + (size_t)(KT + KE + i0) * DDIM);
    const float4* E1 = (const float4*)(E + (size_t)(KT + KE + KD + i1) * DDIM);
    const float4* Bb = (const float4*)outb;

    float4 q;
    float4 v0 = Et[t], v1 = Ee[t], v2 = E0[t], v3 = E1[t], vb = Bb[t];
    q.x = v0.x + v1.x + v2.x + v3.x + vb.x;
    q.y = v0.y + v1.y + v2.y + v3.y + vb.y;
    q.z = v0.z + v1.z + v2.z + v3.z + vb.z;
    q.w = v0.w + v1.w + v2.w + v3.w + vb.w;
    ((float4*)(qout + (size_t)n * DDIM))[t] = q;

    float4 c = ((const float4*)(cb1 + (size_t)i1 * DDIM))[t];
    float4 r = ((const float4*)(resid + (size_t)n * DDIM))[t];
    float dx = c.x - r.x, dy = c.y - r.y, dz = c.z - r.z, dw = c.w - r.w;
    float s1 = dx * dx + dy * dy + dz * dz + dw * dw;
    float ts = blockReduceSum128(s1);
    if (t == 0) atomicAdd(&lacc[3], ts);
}

__global__ void zero_lacc(float* lacc)
{
    if (threadIdx.x < 4) lacc[threadIdx.x] = 0.f;
}

__global__ void write_loss(const float* __restrict__ lacc, float* __restrict__ out)
{
    if (threadIdx.x == 0) {
        float total = lacc[0] + lacc[1] + lacc[2] + lacc[3];
        out[0] = 1.25f * total * (1.0f / ((float)NTOK * (float)DDIM));
    }
}

// ---------------- host ----------------
extern "C" void kernel_launch(void* const* d_in, const int* in_sizes, int n_in,
                              void* d_out, int out_size)
{
    const float* x   = (const float*)d_in[0];
    const float* tW  = (const float*)d_in[1];
    const float* tb  = (const float*)d_in[2];
    const float* eW  = (const float*)d_in[3];
    const float* eb  = (const float*)d_in[4];
    const float* dW  = (const float*)d_in[5];
    const float* db  = (const float*)d_in[6];
    const float* oW  = (const float*)d_in[7];
    const float* ob  = (const float*)d_in[8];
    const float* tcb = (const float*)d_in[9];
    const float* ecb = (const float*)d_in[10];
    const float* cb0 = (const float*)d_in[11];
    const float* cb1 = (const float*)d_in[12];

    float* out = (float*)d_out;
    float* q_out    = out;                               // [NTOK*DDIM]
    float* idxf     = out + (size_t)NTOK * DDIM;         // 4x [NTOK]
    float* loss_out = idxf + (size_t)4 * NTOK;           // [1]

    float *tfeat, *efeat, *dfeat, *resid, *rown, *E, *cn, *lacc;
    int* idx;
    cudaGetSymbolAddress((void**)&tfeat, g_tfeat);
    cudaGetSymbolAddress((void**)&efeat, g_efeat);
    cudaGetSymbolAddress((void**)&dfeat, g_dfeat);
    cudaGetSymbolAddress((void**)&resid, g_resid);
    cudaGetSymbolAddress((void**)&rown,  g_rown);
    cudaGetSymbolAddress((void**)&idx,   g_idx);
    cudaGetSymbolAddress((void**)&E,     g_E);
    cudaGetSymbolAddress((void**)&cn,    g_cn);
    cudaGetSymbolAddress((void**)&lacc,  g_lacc);

    zero_lacc<<<1, 32>>>(lacc);

    // 3 feature linears (+ fused rownorm partials) in one launch
    dim3 gfeat(DDIM / TBN, NTOK / TBM, 3);
    feat3_gemm<<<gfeat, 128>>>(x, tW, tb, eW, eb, dW, db, tfeat, efeat, dfeat);

    // combine rownorm partials (deterministic order)
    combine_rown<<<3 * NTOK / 256, 256>>>();

    // all codebook norms, one launch
    cbnorm<<<KTOT, 128>>>(tcb, ecb, cb0, cb1, cn);

    // projected codebooks, one fused launch: E = cb @ oW_slice^T
    eproj_gemm<<<dim3(DDIM / TBN, 14), 128>>>(tcb, ecb, cb0, cb1, oW, E);

    // first 3 VQ stages fused
    dim3 gvq(NTOK / TBM, 3);
    vq3<<<gvq, 128>>>(tfeat, efeat, dfeat, tcb, ecb, cb0, rown, cn, idx, idxf);

    // residual + losses for first three quantizers
    resid_loss<<<NTOK, 128>>>(tfeat, efeat, dfeat, tcb, ecb, cb0, idx,
                              resid, rown + 3 * NTOK, lacc);

    // second detail stage on residual
    vq1<<<NTOK / TBM, 128>>>(resid, cb1, rown + 3 * NTOK,
                             cn + KT + KE + KD, KD,
                             idx + 3 * NTOK, idxf + 3 * NTOK);

    // gather-add projected codebooks -> quantized output; stage-1 loss
    finalize_out<<<NTOK, 128>>>(E, ob, cb1, resid, idx, q_out, lacc);

    write_loss<<<1, 32>>>(lacc, loss_out);
}

// round 10
// speedup vs baseline: 1.6354x; 1.0936x over previous
#include <cuda_runtime.h>

#define NTOK 65536
#define DDIM 512
#define KT 512
#define KE 256
#define KD 512
#define KTOT (KT + KE + KD + KD)

// ---------------- scratch (device globals; no runtime alloc) ----------------
__device__ float g_tfeat[(size_t)NTOK * DDIM];
__device__ float g_efeat[(size_t)NTOK * DDIM];
__device__ float g_dfeat[(size_t)NTOK * DDIM];
__device__ float g_resid[(size_t)NTOK * DDIM];
__device__ float g_rown[4 * NTOK];           // |f|^2 per token per stage
__device__ float g_rpart[12 * NTOK];         // per-colblock partial |f|^2 (3 stages x 4 blocks)
__device__ int   g_idx[4 * NTOK];            // argmin indices per stage
__device__ float g_E[(size_t)KTOT * DDIM];   // projected codebooks Et,Ee,E0,E1
__device__ float g_cn[KTOT];                 // |c|^2 per code
__device__ float g_lacc[4];                  // loss sum accumulators (sum of d_min per stage)

// ---------------- packed fp32x2 helpers ----------------
#define FMA2(d, a, b) asm("fma.rn.f32x2 %0, %1, %2, %0;" : "+l"(d) : "l"(a), "l"(b))
#define PACK2(d, x, y) asm("mov.b64 %0, {%1, %2};" : "=l"(d) : "f"(x), "f"(y))
#define UNPACK2(x, y, d) asm("mov.b64 {%0, %1}, %2;" : "=f"(x), "=f"(y) : "l"(d))

// ---------------- 128x128x16 tile, 128 threads, 16x8 micro-tile --------------
#define TBM 128
#define TBN 128
#define TBK 16
#define PADW 132
#define STAGE (2 * TBK * PADW)   // As + Bs, one stage (floats)
#define SMEMF (2 * STAGE)        // double buffered

__device__ __forceinline__ void ldg_tile(const float* Ap, const float* Bp,
                                         int lda, int ldb, int ko,
                                         float4 a[4], float4 b[4])
{
    #pragma unroll
    for (int p = 0; p < 4; p++) {
        a[p] = *(const float4*)(Ap + (size_t)(32 * p) * lda + ko);
        b[p] = *(const float4*)(Bp + (size_t)(32 * p) * ldb + ko);
    }
}

__device__ __forceinline__ void sts_tile(float* s, int str, int sto,
                                         const float4 a[4], const float4 b[4])
{
    float* As_ = s;
    float* Bs_ = s + TBK * PADW;
    #pragma unroll
    for (int p = 0; p < 4; p++) {
        int r = str + 32 * p;
        As_[(sto + 0) * PADW + r] = a[p].x;
        As_[(sto + 1) * PADW + r] = a[p].y;
        As_[(sto + 2) * PADW + r] = a[p].z;
        As_[(sto + 3) * PADW + r] = a[p].w;
        Bs_[(sto + 0) * PADW + r] = b[p].x;
        Bs_[(sto + 1) * PADW + r] = b[p].y;
        Bs_[(sto + 2) * PADW + r] = b[p].z;
        Bs_[(sto + 3) * PADW + r] = b[p].w;
    }
}

// acc[ip][j]: row-pair ip (rows tm*16+2ip, +2ip+1) x col j (tn*8+j)
__device__ __forceinline__ void mm_tile(const float* s, int tm, int tn,
                                        unsigned long long acc[8][8])
{
    const float* As_ = s;
    const float* Bs_ = s + TBK * PADW;
    #pragma unroll
    for (int k = 0; k < TBK; k++) {
        const float* ap = &As_[k * PADW + tm * 16];
        const float* bp = &Bs_[k * PADW + tn * 8];
        float4 a0 = *(const float4*)ap;
        float4 a1 = *(const float4*)(ap + 4);
        float4 a2 = *(const float4*)(ap + 8);
        float4 a3 = *(const float4*)(ap + 12);
        float4 b0 = *(const float4*)bp;
        float4 b1 = *(const float4*)(bp + 4);
        unsigned long long ap8[8];
        PACK2(ap8[0], a0.x, a0.y); PACK2(ap8[1], a0.z, a0.w);
        PACK2(ap8[2], a1.x, a1.y); PACK2(ap8[3], a1.z, a1.w);
        PACK2(ap8[4], a2.x, a2.y); PACK2(ap8[5], a2.z, a2.w);
        PACK2(ap8[6], a3.x, a3.y); PACK2(ap8[7], a3.z, a3.w);
        float bv[8] = {b0.x, b0.y, b0.z, b0.w, b1.x, b1.y, b1.z, b1.w};
        #pragma unroll
        for (int j = 0; j < 8; j++) {
            unsigned long long bb;
            PACK2(bb, bv[j], bv[j]);
            #pragma unroll
            for (int i = 0; i < 8; i++)
                FMA2(acc[i][j], ap8[i], bb);
        }
    }
}

// mainloop filling acc; leaves smem free for reuse after final barrier
__device__ __forceinline__ void gemm_mainloop(
    const float* A, int lda, const float* B, int ldb, int Kd,
    int row0, int col0, float* smem, unsigned long long acc[8][8])
{
    int t = threadIdx.x;
    int str = t >> 2, sto = (t & 3) * 4;
    int tm = t >> 4, tn = t & 15;
    const float* Ap = A + (size_t)(row0 + str) * lda + sto;
    const float* Bp = B + (size_t)(col0 + str) * ldb + sto;
    float4 ar[4], br[4];
    ldg_tile(Ap, Bp, lda, ldb, 0, ar, br);
    sts_tile(smem, str, sto, ar, br);
    __syncthreads();
    int nt = Kd / TBK;
    for (int kt = 0; kt < nt; kt++) {
        if (kt + 1 < nt) ldg_tile(Ap, Bp, lda, ldb, (kt + 1) * TBK, ar, br);
        mm_tile(smem + (kt & 1) * STAGE, tm, tn, acc);
        if (kt + 1 < nt) sts_tile(smem + ((kt + 1) & 1) * STAGE, str, sto, ar, br);
        __syncthreads();
    }
}

// ---- fused 3 feature linears + per-colblock row sumsq partials --------------
__global__ __launch_bounds__(128, 2) void feat3_gemm(
    const float* __restrict__ x,
    const float* __restrict__ tW, const float* __restrict__ tb,
    const float* __restrict__ eW, const float* __restrict__ eb,
    const float* __restrict__ dW, const float* __restrict__ db,
    float* __restrict__ tf, float* __restrict__ ef, float* __restrict__ df)
{
    __shared__ float smem[SMEMF];
    int z = blockIdx.z;
    const float* W = (z == 0) ? tW : (z == 1) ? eW : dW;
    const float* bias = (z == 0) ? tb : (z == 1) ? eb : db;
    float* C = (z == 0) ? tf : (z == 1) ? ef : df;
    int row0 = blockIdx.y * TBM, col0 = blockIdx.x * TBN;

    unsigned long long acc[8][8] = {};
    gemm_mainloop(x, DDIM, W, DDIM, DDIM, row0, col0, smem, acc);

    int t = threadIdx.x;
    int tm = t >> 4, tn = t & 15;
    float* s_sq = smem;                       // [128][17] alias, safe after final barrier
    #pragma unroll
    for (int ip = 0; ip < 8; ip++) {
        float lo[8], hi[8];
        #pragma unroll
        for (int j = 0; j < 8; j++) UNPACK2(lo[j], hi[j], acc[ip][j]);
        int r0 = row0 + tm * 16 + 2 * ip;
        int c0 = col0 + tn * 8;
        float plo = 0.f, phi = 0.f;
        #pragma unroll
        for (int j = 0; j < 8; j++) {
            float bb = bias[c0 + j];
            lo[j] += bb; hi[j] += bb;
            plo += lo[j] * lo[j];
            phi += hi[j] * hi[j];
        }
        float4 w0 = {lo[0], lo[1], lo[2], lo[3]};
        float4 w1 = {lo[4], lo[5], lo[6], lo[7]};
        float4 w2 = {hi[0], hi[1], hi[2], hi[3]};
        float4 w3 = {hi[4], hi[5], hi[6], hi[7]};
        *(float4*)(C + (size_t)r0 * DDIM + c0) = w0;
        *(float4*)(C + (size_t)r0 * DDIM + c0 + 4) = w1;
        *(float4*)(C + (size_t)(r0 + 1) * DDIM + c0) = w2;
        *(float4*)(C + (size_t)(r0 + 1) * DDIM + c0 + 4) = w3;
        s_sq[(tm * 16 + 2 * ip) * 17 + tn] = plo;
        s_sq[(tm * 16 + 2 * ip + 1) * 17 + tn] = phi;
    }
    __syncthreads();
    if (t < TBM) {
        float s = 0.f;
        #pragma unroll
        for (int c = 0; c < 16; c++) s += s_sq[t * 17 + c];
        g_rpart[(size_t)(z * 4 + blockIdx.x) * NTOK + row0 + t] = s;
    }
}

// deterministic 4-way combine of colblock partials -> g_rown[stage][row]
__global__ void combine_rown()
{
    int i = blockIdx.x * 256 + threadIdx.x;  // i < 3*NTOK
    int z = i / NTOK, r = i - z * NTOK;
    const float* p = g_rpart + (size_t)(z * 4) * NTOK + r;
    float s = ((p[0] + p[(size_t)NTOK]) + p[(size_t)2 * NTOK]) + p[(size_t)3 * NTOK];
    g_rown[z * NTOK + r] = s;
}

// ---- fused E-projection: E = cb @ oW_slice^T (4 small GEMMs, one launch) ----
__global__ __launch_bounds__(128, 2) void eproj_gemm(
    const float* __restrict__ tcb, const float* __restrict__ ecb,
    const float* __restrict__ cb0, const float* __restrict__ cb1,
    const float* __restrict__ oW, float* __restrict__ E)
{
    __shared__ float smem[SMEMF];
    int y = blockIdx.y;
    const float* A;
    int boff, rb;
    size_t coff;
    if (y < 4)       { A = tcb; boff = 0;        coff = 0;            rb = y; }
    else if (y < 6)  { A = ecb; boff = DDIM;     coff = KT;           rb = y - 4; }
    else if (y < 10) { A = cb0; boff = 2 * DDIM; coff = KT + KE;      rb = y - 6; }
    else             { A = cb1; boff = 2 * DDIM; coff = KT + KE + KD; rb = y - 10; }
    int row0 = rb * TBM, col0 = blockIdx.x * TBN;

    unsigned long long acc[8][8] = {};
    gemm_mainloop(A, DDIM, oW + boff, 3 * DDIM, DDIM, row0, col0, smem, acc);

    int t = threadIdx.x;
    int tm = t >> 4, tn = t & 15;
    float* C = E + coff * DDIM;
    #pragma unroll
    for (int ip = 0; ip < 8; ip++) {
        float lo[8], hi[8];
        #pragma unroll
        for (int j = 0; j < 8; j++) UNPACK2(lo[j], hi[j], acc[ip][j]);
        int r0 = row0 + tm * 16 + 2 * ip;
        int c0 = col0 + tn * 8;
        float4 w0 = {lo[0], lo[1], lo[2], lo[3]};
        float4 w1 = {lo[4], lo[5], lo[6], lo[7]};
        float4 w2 = {hi[0], hi[1], hi[2], hi[3]};
        float4 w3 = {hi[4], hi[5], hi[6], hi[7]};
        *(float4*)(C + (size_t)r0 * DDIM + c0) = w0;
        *(float4*)(C + (size_t)r0 * DDIM + c0 + 4) = w1;
        *(float4*)(C + (size_t)(r0 + 1) * DDIM + c0) = w2;
        *(float4*)(C + (size_t)(r0 + 1) * DDIM + c0 + 4) = w3;
    }
}

// ---------------- fused distance GEMM + rowwise argmin + loss accumulation ---
// loss identity: ||f - c_idx||^2 == d_min, so stage loss = sum over rows of bv.
__device__ __forceinline__ void vq_block(
    const float* feat, const float* cb, const float* rown_,
    const float* cnorm, int Kcodes,
    int* idx_out, float* idxf_out, float* loss_slot, int row0, float* smem)
{
    int t = threadIdx.x;
    int tm = t >> 4, tn = t & 15;

    float bestv[16];
    int bidx[16];
    #pragma unroll
    for (int i = 0; i < 16; i++) { bestv[i] = 3.4e38f; bidx[i] = 0; }

    for (int nc = 0; nc < Kcodes; nc += TBN) {
        unsigned long long acc[8][8] = {};
        gemm_mainloop(feat, DDIM, cb + (size_t)nc * DDIM, DDIM, DDIM,
                      row0, 0, smem, acc);
        float cw[8];
        #pragma unroll
        for (int j = 0; j < 8; j++) cw[j] = cnorm[nc + tn * 8 + j];
        #pragma unroll
        for (int ip = 0; ip < 8; ip++) {
            float lo[8], hi[8];
            #pragma unroll
            for (int j = 0; j < 8; j++) UNPACK2(lo[j], hi[j], acc[ip][j]);
            float An0 = rown_[row0 + tm * 16 + 2 * ip];
            float An1 = rown_[row0 + tm * 16 + 2 * ip + 1];
            #pragma unroll
            for (int j = 0; j < 8; j++) {
                int code = nc + tn * 8 + j;
                float d0 = (An0 + cw[j]) - 2.0f * lo[j];
                if (d0 < bestv[2 * ip]) { bestv[2 * ip] = d0; bidx[2 * ip] = code; }
                float d1 = (An1 + cw[j]) - 2.0f * hi[j];
                if (d1 < bestv[2 * ip + 1]) { bestv[2 * ip + 1] = d1; bidx[2 * ip + 1] = code; }
            }
        }
        __syncthreads();   // protect smem reuse across nc iterations
    }

    // cross-thread reduce (alias smem)
    float* sval = smem;                 // [128][16]
    int*   sidx = (int*)(smem + 2048);  // [128][16]
    #pragma unroll
    for (int i = 0; i < 16; i++) {
        sval[(tm * 16 + i) * 16 + tn] = bestv[i];
        sidx[(tm * 16 + i) * 16 + tn] = bidx[i];
    }
    __syncthreads();
    // every thread owns one row (block has exactly TBM threads)
    float bv = 3.4e38f;
    int bi = 0x7fffffff;
    #pragma unroll
    for (int c = 0; c < 16; c++) {
        float v = sval[t * 16 + c];
        int id = sidx[t * 16 + c];
        if (v < bv || (v == bv && id < bi)) { bv = v; bi = id; }
    }
    idx_out[row0 + t] = bi;
    idxf_out[row0 + t] = (float)bi;

    // block-sum of winning distances -> stage loss accumulator
    __syncthreads();
    float* sred = smem;
    sred[t] = bv;
    __syncthreads();
    for (int s = 64; s > 0; s >>= 1) {
        if (t < s) sred[t] += sred[t + s];
        __syncthreads();
    }
    if (t == 0) atomicAdd(loss_slot, sred[0]);
}

// fused first-3 VQ stages (y selects stage)
__global__ __launch_bounds__(128, 2) void vq3(
    const float* __restrict__ tf, const float* __restrict__ ef,
    const float* __restrict__ df,
    const float* __restrict__ tcb, const float* __restrict__ ecb,
    const float* __restrict__ cb0,
    const float* __restrict__ rown_, const float* __restrict__ cn_,
    int* __restrict__ idx_, float* __restrict__ idxf_,
    float* __restrict__ lacc)
{
    __shared__ float smem[SMEMF];
    int s = blockIdx.y;
    const float* feat = (s == 0) ? tf : (s == 1) ? ef : df;
    const float* cb   = (s == 0) ? tcb : (s == 1) ? ecb : cb0;
    const float* rn   = rown_ + s * NTOK;
    const float* cn   = (s == 0) ? cn_ : (s == 1) ? (cn_ + KT) : (cn_ + KT + KE);
    int Kc            = (s == 1) ? KE : KT;
    vq_block(feat, cb, rn, cn, Kc, idx_ + s * NTOK, idxf_ + s * NTOK,
             lacc + s, blockIdx.x * TBM, smem);
}

__global__ __launch_bounds__(128, 2) void vq1(
    const float* __restrict__ feat, const float* __restrict__ cb,
    const float* __restrict__ rown_, const float* __restrict__ cnorm,
    int Kcodes, int* __restrict__ idx_out, float* __restrict__ idxf_out,
    float* __restrict__ loss_slot)
{
    __shared__ float smem[SMEMF];
    vq_block(feat, cb, rown_, cnorm, Kcodes, idx_out, idxf_out,
             loss_slot, blockIdx.x * TBM, smem);
}

// ---------------- helpers ----------------
__device__ __forceinline__ float blockReduceSum128(float v)
{
    __shared__ float sm[128];
    int t = threadIdx.x;
    sm[t] = v;
    __syncthreads();
    for (int s = 64; s > 0; s >>= 1) {
        if (t < s) sm[t] += sm[t + s];
        __syncthreads();
    }
    float r = sm[0];
    __syncthreads();
    return r;
}

// all 4 codebook norms in one launch
__global__ __launch_bounds__(128) void cbnorm(
    const float* __restrict__ tcb, const float* __restrict__ ecb,
    const float* __restrict__ cb0, const float* __restrict__ cb1,
    float* __restrict__ out)
{
    int row = blockIdx.x;
    const float* src;
    if (row < KT)                src = tcb + (size_t)row * DDIM;
    else if (row < KT + KE)      src = ecb + (size_t)(row - KT) * DDIM;
    else if (row < KT + KE + KD) src = cb0 + (size_t)(row - KT - KE) * DDIM;
    else                         src = cb1 + (size_t)(row - KT - KE - KD) * DDIM;
    int t = threadIdx.x;
    float4 v = ((const float4*)src)[t];
    float s = v.x * v.x + v.y * v.y + v.z * v.z + v.w * v.w;
    float tot = blockReduceSum128(s);
    if (t == 0) out[row] = tot;
}

// residual only: resid = dfeat - cb0[idx0], |resid|^2 per row (losses come from vq)
__global__ __launch_bounds__(128) void make_resid(
    const float* __restrict__ df, const float* __restrict__ cb0,
    const int* __restrict__ idx,
    float* __restrict__ resid, float* __restrict__ rownR)
{
    int n = blockIdx.x;
    int t = threadIdx.x;
    int i0 = idx[2 * NTOK + n];

    float4 a = ((const float4*)(df + (size_t)n * DDIM))[t];
    float4 c = ((const float4*)(cb0 + (size_t)i0 * DDIM))[t];
    float4 r;
    r.x = a.x - c.x; r.y = a.y - c.y; r.z = a.z - c.z; r.w = a.w - c.w;
    ((float4*)(resid + (size_t)n * DDIM))[t] = r;
    float sr = r.x * r.x + r.y * r.y + r.z * r.z + r.w * r.w;
    float tr = blockReduceSum128(sr);
    if (t == 0) rownR[n] = tr;
}

// gather-add of projected codebooks + out bias -> quantized
__global__ __launch_bounds__(128) void finalize_out(
    const float* __restrict__ E,
    const float* __restrict__ outb,
    const int* __restrict__ idx,
    float* __restrict__ qout)
{
    int n = blockIdx.x;
    int t = threadIdx.x;
    int it = idx[0 * NTOK + n];
    int ie = idx[1 * NTOK + n];
    int i0 = idx[2 * NTOK + n];
    int i1 = idx[3 * NTOK + n];

    const float4* Et = (const float4*)(E + (size_t)it * DDIM);
    const float4* Ee = (const float4*)(E + (size_t)(KT + ie) * DDIM);
    const float4* E0 = (const float4*)(E + (size_t)(KT + KE + i0) * DDIM);
    const float4* E1 = (const float4*)(E + (size_t)(KT + KE + KD + i1) * DDIM);
    const float4* Bb = (const float4*)outb;

    float4 q;
    float4 v0 = Et[t], v1 = Ee[t], v2 = E0[t], v3 = E1[t], vb = Bb[t];
    q.x = v0.x + v1.x + v2.x + v3.x + vb.x;
    q.y = v0.y + v1.y + v2.y + v3.y + vb.y;
    q.z = v0.z + v1.z + v2.z + v3.z + vb.z;
    q.w = v0.w + v1.w + v2.w + v3.w + vb.w;
    ((float4*)(qout + (size_t)n * DDIM))[t] = q;
}

__global__ void zero_lacc(float* lacc)
{
    if (threadIdx.x < 4) lacc[threadIdx.x] = 0.f;
}

__global__ void write_loss(const float* __restrict__ lacc, float* __restrict__ out)
{
    if (threadIdx.x == 0) {
        float total = lacc[0] + lacc[1] + lacc[2] + lacc[3];
        out[0] = 1.25f * total * (1.0f / ((float)NTOK * (float)DDIM));
    }
}

// ---------------- host ----------------
extern "C" void kernel_launch(void* const* d_in, const int* in_sizes, int n_in,
                              void* d_out, int out_size)
{
    const float* x   = (const float*)d_in[0];
    const float* tW  = (const float*)d_in[1];
    const float* tb  = (const float*)d_in[2];
    const float* eW  = (const float*)d_in[3];
    const float* eb  = (const float*)d_in[4];
    const float* dW  = (const float*)d_in[5];
    const float* db  = (const float*)d_in[6];
    const float* oW  = (const float*)d_in[7];
    const float* ob  = (const float*)d_in[8];
    const float* tcb = (const float*)d_in[9];
    const float* ecb = (const float*)d_in[10];
    const float* cb0 = (const float*)d_in[11];
    const float* cb1 = (const float*)d_in[12];

    float* out = (float*)d_out;
    float* q_out    = out;                               // [NTOK*DDIM]
    float* idxf     = out + (size_t)NTOK * DDIM;         // 4x [NTOK]
    float* loss_out = idxf + (size_t)4 * NTOK;           // [1]

    float *tfeat, *efeat, *dfeat, *resid, *rown, *E, *cn, *lacc;
    int* idx;
    cudaGetSymbolAddress((void**)&tfeat, g_tfeat);
    cudaGetSymbolAddress((void**)&efeat, g_efeat);
    cudaGetSymbolAddress((void**)&dfeat, g_dfeat);
    cudaGetSymbolAddress((void**)&resid, g_resid);
    cudaGetSymbolAddress((void**)&rown,  g_rown);
    cudaGetSymbolAddress((void**)&idx,   g_idx);
    cudaGetSymbolAddress((void**)&E,     g_E);
    cudaGetSymbolAddress((void**)&cn,    g_cn);
    cudaGetSymbolAddress((void**)&lacc,  g_lacc);

    zero_lacc<<<1, 32>>>(lacc);

    // 3 feature linears (+ fused rownorm partials) in one launch
    dim3 gfeat(DDIM / TBN, NTOK / TBM, 3);
    feat3_gemm<<<gfeat, 128>>>(x, tW, tb, eW, eb, dW, db, tfeat, efeat, dfeat);

    // combine rownorm partials (deterministic order)
    combine_rown<<<3 * NTOK / 256, 256>>>();

    // all codebook norms, one launch
    cbnorm<<<KTOT, 128>>>(tcb, ecb, cb0, cb1, cn);

    // projected codebooks, one fused launch: E = cb @ oW_slice^T
    eproj_gemm<<<dim3(DDIM / TBN, 14), 128>>>(tcb, ecb, cb0, cb1, oW, E);

    // first 3 VQ stages fused (losses accumulated in-kernel from d_min)
    dim3 gvq(NTOK / TBM, 3);
    vq3<<<gvq, 128>>>(tfeat, efeat, dfeat, tcb, ecb, cb0, rown, cn,
                      idx, idxf, lacc);

    // residual for stage-2 detail (no loss math here)
    make_resid<<<NTOK, 128>>>(dfeat, cb0, idx, resid, rown + 3 * NTOK);

    // second detail stage on residual (loss -> lacc[3])
    vq1<<<NTOK / TBM, 128>>>(resid, cb1, rown + 3 * NTOK,
                             cn + KT + KE + KD, KD,
                             idx + 3 * NTOK, idxf + 3 * NTOK, lacc + 3);

    // gather-add projected codebooks -> quantized output
    finalize_out<<<NTOK, 128>>>(E, ob, idx, q_out);

    write_loss<<<1, 32>>>(lacc, loss_out);
}

// round 11
// speedup vs baseline: 1.6597x; 1.0149x over previous
#include <cuda_runtime.h>

#define NTOK 65536
#define DDIM 512
#define KT 512
#define KE 256
#define KD 512
#define KTOT (KT + KE + KD + KD)

// ---------------- scratch (device globals; no runtime alloc) ----------------
__device__ float g_tfeat[(size_t)NTOK * DDIM];
__device__ float g_efeat[(size_t)NTOK * DDIM];
__device__ float g_dfeat[(size_t)NTOK * DDIM];
__device__ float g_resid[(size_t)NTOK * DDIM];
__device__ float g_rown[4 * NTOK];           // |f|^2 per token per stage
__device__ float g_rpart[12 * NTOK];         // per-colblock partial |f|^2 (3 stages x 4 blocks)
__device__ int   g_idx[4 * NTOK];            // argmin indices per stage
__device__ float g_E[(size_t)KTOT * DDIM];   // projected codebooks Et,Ee,E0,E1
__device__ float g_cn[KTOT];                 // |c|^2 per code
__device__ float g_lacc[4];                  // loss sum accumulators (sum of d_min per stage)

// ---------------- packed fp32x2 helpers ----------------
#define FMA2(d, a, b) asm("fma.rn.f32x2 %0, %1, %2, %0;" : "+l"(d) : "l"(a), "l"(b))
#define PACK2(d, x, y) asm("mov.b64 %0, {%1, %2};" : "=l"(d) : "f"(x), "f"(y))
#define UNPACK2(x, y, d) asm("mov.b64 {%0, %1}, %2;" : "=f"(x), "=f"(y) : "l"(d))

// ---------------- 128x128x16 tile, 128 threads, 16x8 micro-tile --------------
#define TBM 128
#define TBN 128
#define TBK 16
#define PADW 132
#define STAGE (2 * TBK * PADW)   // As + Bs, one stage (floats)
#define SMEMF (2 * STAGE)        // double buffered

__device__ __forceinline__ void ldg_tile(const float* Ap, const float* Bp,
                                         int lda, int ldb, int ko,
                                         float4 a[4], float4 b[4])
{
    #pragma unroll
    for (int p = 0; p < 4; p++) {
        a[p] = *(const float4*)(Ap + (size_t)(32 * p) * lda + ko);
        b[p] = *(const float4*)(Bp + (size_t)(32 * p) * ldb + ko);
    }
}

__device__ __forceinline__ void sts_tile(float* s, int str, int sto,
                                         const float4 a[4], const float4 b[4])
{
    float* As_ = s;
    float* Bs_ = s + TBK * PADW;
    #pragma unroll
    for (int p = 0; p < 4; p++) {
        int r = str + 32 * p;
        As_[(sto + 0) * PADW + r] = a[p].x;
        As_[(sto + 1) * PADW + r] = a[p].y;
        As_[(sto + 2) * PADW + r] = a[p].z;
        As_[(sto + 3) * PADW + r] = a[p].w;
        Bs_[(sto + 0) * PADW + r] = b[p].x;
        Bs_[(sto + 1) * PADW + r] = b[p].y;
        Bs_[(sto + 2) * PADW + r] = b[p].z;
        Bs_[(sto + 3) * PADW + r] = b[p].w;
    }
}

// acc[ip][j]: row-pair ip (rows tm*16+2ip, +2ip+1) x col j (tn*8+j)
__device__ __forceinline__ void mm_tile(const float* s, int tm, int tn,
                                        unsigned long long acc[8][8])
{
    const float* As_ = s;
    const float* Bs_ = s + TBK * PADW;
    #pragma unroll
    for (int k = 0; k < TBK; k++) {
        const float* ap = &As_[k * PADW + tm * 16];
        const float* bp = &Bs_[k * PADW + tn * 8];
        float4 a0 = *(const float4*)ap;
        float4 a1 = *(const float4*)(ap + 4);
        float4 a2 = *(const float4*)(ap + 8);
        float4 a3 = *(const float4*)(ap + 12);
        float4 b0 = *(const float4*)bp;
        float4 b1 = *(const float4*)(bp + 4);
        unsigned long long ap8[8];
        PACK2(ap8[0], a0.x, a0.y); PACK2(ap8[1], a0.z, a0.w);
        PACK2(ap8[2], a1.x, a1.y); PACK2(ap8[3], a1.z, a1.w);
        PACK2(ap8[4], a2.x, a2.y); PACK2(ap8[5], a2.z, a2.w);
        PACK2(ap8[6], a3.x, a3.y); PACK2(ap8[7], a3.z, a3.w);
        float bv[8] = {b0.x, b0.y, b0.z, b0.w, b1.x, b1.y, b1.z, b1.w};
        #pragma unroll
        for (int j = 0; j < 8; j++) {
            unsigned long long bb;
            PACK2(bb, bv[j], bv[j]);
            #pragma unroll
            for (int i = 0; i < 8; i++)
                FMA2(acc[i][j], ap8[i], bb);
        }
    }
}

// mainloop filling acc; leaves smem free for reuse after final barrier
__device__ __forceinline__ void gemm_mainloop(
    const float* A, int lda, const float* B, int ldb, int Kd,
    int row0, int col0, float* smem, unsigned long long acc[8][8])
{
    int t = threadIdx.x;
    int str = t >> 2, sto = (t & 3) * 4;
    int tm = t >> 4, tn = t & 15;
    const float* Ap = A + (size_t)(row0 + str) * lda + sto;
    const float* Bp = B + (size_t)(col0 + str) * ldb + sto;
    float4 ar[4], br[4];
    ldg_tile(Ap, Bp, lda, ldb, 0, ar, br);
    sts_tile(smem, str, sto, ar, br);
    __syncthreads();
    int nt = Kd / TBK;
    for (int kt = 0; kt < nt; kt++) {
        if (kt + 1 < nt) ldg_tile(Ap, Bp, lda, ldb, (kt + 1) * TBK, ar, br);
        mm_tile(smem + (kt & 1) * STAGE, tm, tn, acc);
        if (kt + 1 < nt) sts_tile(smem + ((kt + 1) & 1) * STAGE, str, sto, ar, br);
        __syncthreads();
    }
}

// ---- fused 3 feature linears + per-colblock row sumsq partials --------------
__global__ __launch_bounds__(128, 2) void feat3_gemm(
    const float* __restrict__ x,
    const float* __restrict__ tW, const float* __restrict__ tb,
    const float* __restrict__ eW, const float* __restrict__ eb,
    const float* __restrict__ dW, const float* __restrict__ db,
    float* __restrict__ tf, float* __restrict__ ef, float* __restrict__ df)
{
    __shared__ float smem[SMEMF];
    int z = blockIdx.z;
    const float* W = (z == 0) ? tW : (z == 1) ? eW : dW;
    const float* bias = (z == 0) ? tb : (z == 1) ? eb : db;
    float* C = (z == 0) ? tf : (z == 1) ? ef : df;
    int row0 = blockIdx.y * TBM, col0 = blockIdx.x * TBN;

    unsigned long long acc[8][8] = {};
    gemm_mainloop(x, DDIM, W, DDIM, DDIM, row0, col0, smem, acc);

    int t = threadIdx.x;
    int tm = t >> 4, tn = t & 15;
    float* s_sq = smem;                       // [128][17] alias, safe after final barrier
    #pragma unroll
    for (int ip = 0; ip < 8; ip++) {
        float lo[8], hi[8];
        #pragma unroll
        for (int j = 0; j < 8; j++) UNPACK2(lo[j], hi[j], acc[ip][j]);
        int r0 = row0 + tm * 16 + 2 * ip;
        int c0 = col0 + tn * 8;
        float plo = 0.f, phi = 0.f;
        #pragma unroll
        for (int j = 0; j < 8; j++) {
            float bb = bias[c0 + j];
            lo[j] += bb; hi[j] += bb;
            plo += lo[j] * lo[j];
            phi += hi[j] * hi[j];
        }
        float4 w0 = {lo[0], lo[1], lo[2], lo[3]};
        float4 w1 = {lo[4], lo[5], lo[6], lo[7]};
        float4 w2 = {hi[0], hi[1], hi[2], hi[3]};
        float4 w3 = {hi[4], hi[5], hi[6], hi[7]};
        *(float4*)(C + (size_t)r0 * DDIM + c0) = w0;
        *(float4*)(C + (size_t)r0 * DDIM + c0 + 4) = w1;
        *(float4*)(C + (size_t)(r0 + 1) * DDIM + c0) = w2;
        *(float4*)(C + (size_t)(r0 + 1) * DDIM + c0 + 4) = w3;
        s_sq[(tm * 16 + 2 * ip) * 17 + tn] = plo;
        s_sq[(tm * 16 + 2 * ip + 1) * 17 + tn] = phi;
    }
    __syncthreads();
    if (t < TBM) {
        float s = 0.f;
        #pragma unroll
        for (int c = 0; c < 16; c++) s += s_sq[t * 17 + c];
        g_rpart[(size_t)(z * 4 + blockIdx.x) * NTOK + row0 + t] = s;
    }
}

// deterministic 4-way combine of colblock partials -> g_rown[stage][row]
__global__ void combine_rown()
{
    int i = blockIdx.x * 256 + threadIdx.x;  // i < 3*NTOK
    int z = i / NTOK, r = i - z * NTOK;
    const float* p = g_rpart + (size_t)(z * 4) * NTOK + r;
    float s = ((p[0] + p[(size_t)NTOK]) + p[(size_t)2 * NTOK]) + p[(size_t)3 * NTOK];
    g_rown[z * NTOK + r] = s;
}

// ---- fused E-projection: E = cb @ oW_slice^T (4 small GEMMs, one launch) ----
__global__ __launch_bounds__(128, 2) void eproj_gemm(
    const float* __restrict__ tcb, const float* __restrict__ ecb,
    const float* __restrict__ cb0, const float* __restrict__ cb1,
    const float* __restrict__ oW, float* __restrict__ E)
{
    __shared__ float smem[SMEMF];
    int y = blockIdx.y;
    const float* A;
    int boff, rb;
    size_t coff;
    if (y < 4)       { A = tcb; boff = 0;        coff = 0;            rb = y; }
    else if (y < 6)  { A = ecb; boff = DDIM;     coff = KT;           rb = y - 4; }
    else if (y < 10) { A = cb0; boff = 2 * DDIM; coff = KT + KE;      rb = y - 6; }
    else             { A = cb1; boff = 2 * DDIM; coff = KT + KE + KD; rb = y - 10; }
    int row0 = rb * TBM, col0 = blockIdx.x * TBN;

    unsigned long long acc[8][8] = {};
    gemm_mainloop(A, DDIM, oW + boff, 3 * DDIM, DDIM, row0, col0, smem, acc);

    int t = threadIdx.x;
    int tm = t >> 4, tn = t & 15;
    float* C = E + coff * DDIM;
    #pragma unroll
    for (int ip = 0; ip < 8; ip++) {
        float lo[8], hi[8];
        #pragma unroll
        for (int j = 0; j < 8; j++) UNPACK2(lo[j], hi[j], acc[ip][j]);
        int r0 = row0 + tm * 16 + 2 * ip;
        int c0 = col0 + tn * 8;
        float4 w0 = {lo[0], lo[1], lo[2], lo[3]};
        float4 w1 = {lo[4], lo[5], lo[6], lo[7]};
        float4 w2 = {hi[0], hi[1], hi[2], hi[3]};
        float4 w3 = {hi[4], hi[5], hi[6], hi[7]};
        *(float4*)(C + (size_t)r0 * DDIM + c0) = w0;
        *(float4*)(C + (size_t)r0 * DDIM + c0 + 4) = w1;
        *(float4*)(C + (size_t)(r0 + 1) * DDIM + c0) = w2;
        *(float4*)(C + (size_t)(r0 + 1) * DDIM + c0 + 4) = w3;
    }
}

// ---------------- fused distance GEMM + rowwise argmin + loss accumulation ---
// loss identity: ||f - c_idx||^2 == d_min; stage loss = sum of bv over rows.
// rownR_out (optional): d_min is also |f - c_idx|^2 = |resid|^2 for the next stage.
__device__ __forceinline__ void vq_block(
    const float* feat, const float* cb, const float* rown_,
    const float* cnorm, int Kcodes,
    int* idx_out, float* idxf_out, float* loss_slot, float* rownR_out,
    int row0, float* smem)
{
    int t = threadIdx.x;
    int tm = t >> 4, tn = t & 15;

    float bestv[16];
    int bidx[16];
    #pragma unroll
    for (int i = 0; i < 16; i++) { bestv[i] = 3.4e38f; bidx[i] = 0; }

    for (int nc = 0; nc < Kcodes; nc += TBN) {
        unsigned long long acc[8][8] = {};
        gemm_mainloop(feat, DDIM, cb + (size_t)nc * DDIM, DDIM, DDIM,
                      row0, 0, smem, acc);
        float cw[8];
        #pragma unroll
        for (int j = 0; j < 8; j++) cw[j] = cnorm[nc + tn * 8 + j];
        #pragma unroll
        for (int ip = 0; ip < 8; ip++) {
            float lo[8], hi[8];
            #pragma unroll
            for (int j = 0; j < 8; j++) UNPACK2(lo[j], hi[j], acc[ip][j]);
            float An0 = rown_[row0 + tm * 16 + 2 * ip];
            float An1 = rown_[row0 + tm * 16 + 2 * ip + 1];
            #pragma unroll
            for (int j = 0; j < 8; j++) {
                int code = nc + tn * 8 + j;
                float d0 = (An0 + cw[j]) - 2.0f * lo[j];
                if (d0 < bestv[2 * ip]) { bestv[2 * ip] = d0; bidx[2 * ip] = code; }
                float d1 = (An1 + cw[j]) - 2.0f * hi[j];
                if (d1 < bestv[2 * ip + 1]) { bestv[2 * ip + 1] = d1; bidx[2 * ip + 1] = code; }
            }
        }
        __syncthreads();   // protect smem reuse across nc iterations
    }

    // cross-thread reduce (alias smem)
    float* sval = smem;                 // [128][16]
    int*   sidx = (int*)(smem + 2048);  // [128][16]
    #pragma unroll
    for (int i = 0; i < 16; i++) {
        sval[(tm * 16 + i) * 16 + tn] = bestv[i];
        sidx[(tm * 16 + i) * 16 + tn] = bidx[i];
    }
    __syncthreads();
    // every thread owns one row (block has exactly TBM threads)
    float bv = 3.4e38f;
    int bi = 0x7fffffff;
    #pragma unroll
    for (int c = 0; c < 16; c++) {
        float v = sval[t * 16 + c];
        int id = sidx[t * 16 + c];
        if (v < bv || (v == bv && id < bi)) { bv = v; bi = id; }
    }
    idx_out[row0 + t] = bi;
    idxf_out[row0 + t] = (float)bi;
    if (rownR_out) rownR_out[row0 + t] = bv;   // |resid|^2 for next stage

    // block-sum of winning distances -> stage loss accumulator
    __syncthreads();
    float* sred = smem;
    sred[t] = bv;
    __syncthreads();
    for (int s = 64; s > 0; s >>= 1) {
        if (t < s) sred[t] += sred[t + s];
        __syncthreads();
    }
    if (t == 0) atomicAdd(loss_slot, sred[0]);
}

// fused first-3 VQ stages (y selects stage); detail stage also emits |resid|^2
__global__ __launch_bounds__(128, 2) void vq3(
    const float* __restrict__ tf, const float* __restrict__ ef,
    const float* __restrict__ df,
    const float* __restrict__ tcb, const float* __restrict__ ecb,
    const float* __restrict__ cb0,
    const float* __restrict__ rown_, const float* __restrict__ cn_,
    int* __restrict__ idx_, float* __restrict__ idxf_,
    float* __restrict__ lacc, float* __restrict__ rownR)
{
    __shared__ float smem[SMEMF];
    int s = blockIdx.y;
    const float* feat = (s == 0) ? tf : (s == 1) ? ef : df;
    const float* cb   = (s == 0) ? tcb : (s == 1) ? ecb : cb0;
    const float* rn   = rown_ + s * NTOK;
    const float* cn   = (s == 0) ? cn_ : (s == 1) ? (cn_ + KT) : (cn_ + KT + KE);
    int Kc            = (s == 1) ? KE : KT;
    float* rro        = (s == 2) ? rownR : (float*)0;
    vq_block(feat, cb, rn, cn, Kc, idx_ + s * NTOK, idxf_ + s * NTOK,
             lacc + s, rro, blockIdx.x * TBM, smem);
}

__global__ __launch_bounds__(128, 2) void vq1(
    const float* __restrict__ feat, const float* __restrict__ cb,
    const float* __restrict__ rown_, const float* __restrict__ cnorm,
    int Kcodes, int* __restrict__ idx_out, float* __restrict__ idxf_out,
    float* __restrict__ loss_slot)
{
    __shared__ float smem[SMEMF];
    vq_block(feat, cb, rown_, cnorm, Kcodes, idx_out, idxf_out,
             loss_slot, (float*)0, blockIdx.x * TBM, smem);
}

// ---------------- helpers ----------------
__device__ __forceinline__ float blockReduceSum128(float v)
{
    __shared__ float sm[128];
    int t = threadIdx.x;
    sm[t] = v;
    __syncthreads();
    for (int s = 64; s > 0; s >>= 1) {
        if (t < s) sm[t] += sm[t + s];
        __syncthreads();
    }
    float r = sm[0];
    __syncthreads();
    return r;
}

// all 4 codebook norms in one launch
__global__ __launch_bounds__(128) void cbnorm(
    const float* __restrict__ tcb, const float* __restrict__ ecb,
    const float* __restrict__ cb0, const float* __restrict__ cb1,
    float* __restrict__ out)
{
    int row = blockIdx.x;
    const float* src;
    if (row < KT)                src = tcb + (size_t)row * DDIM;
    else if (row < KT + KE)      src = ecb + (size_t)(row - KT) * DDIM;
    else if (row < KT + KE + KD) src = cb0 + (size_t)(row - KT - KE) * DDIM;
    else                         src = cb1 + (size_t)(row - KT - KE - KD) * DDIM;
    int t = threadIdx.x;
    float4 v = ((const float4*)src)[t];
    float s = v.x * v.x + v.y * v.y + v.z * v.z + v.w * v.w;
    float tot = blockReduceSum128(s);
    if (t == 0) out[row] = tot;
}

// residual only: resid = dfeat - cb0[idx0] (|resid|^2 comes from vq3 d_min)
__global__ __launch_bounds__(128) void make_resid(
    const float* __restrict__ df, const float* __restrict__ cb0,
    const int* __restrict__ idx,
    float* __restrict__ resid)
{
    int n = blockIdx.x;
    int t = threadIdx.x;
    int i0 = idx[2 * NTOK + n];

    float4 a = ((const float4*)(df + (size_t)n * DDIM))[t];
    float4 c = ((const float4*)(cb0 + (size_t)i0 * DDIM))[t];
    float4 r;
    r.x = a.x - c.x; r.y = a.y - c.y; r.z = a.z - c.z; r.w = a.w - c.w;
    ((float4*)(resid + (size_t)n * DDIM))[t] = r;
}

// gather-add of projected codebooks + out bias -> quantized
__global__ __launch_bounds__(128) void finalize_out(
    const float* __restrict__ E,
    const float* __restrict__ outb,
    const int* __restrict__ idx,
    float* __restrict__ qout)
{
    int n = blockIdx.x;
    int t = threadIdx.x;
    int it = idx[0 * NTOK + n];
    int ie = idx[1 * NTOK + n];
    int i0 = idx[2 * NTOK + n];
    int i1 = idx[3 * NTOK + n];

    const float4* Et = (const float4*)(E + (size_t)it * DDIM);
    const float4* Ee = (const float4*)(E + (size_t)(KT + ie) * DDIM);
    const float4* E0 = (const float4*)(E + (size_t)(KT + KE + i0) * DDIM);
    const float4* E1 = (const float4*)(E + (size_t)(KT + KE + KD + i1) * DDIM);
    const float4* Bb = (const float4*)outb;

    float4 q;
    float4 v0 = Et[t], v1 = Ee[t], v2 = E0[t], v3 = E1[t], vb = Bb[t];
    q.x = v0.x + v1.x + v2.x + v3.x + vb.x;
    q.y = v0.y + v1.y + v2.y + v3.y + vb.y;
    q.z = v0.z + v1.z + v2.z + v3.z + vb.z;
    q.w = v0.w + v1.w + v2.w + v3.w + vb.w;
    ((float4*)(qout + (size_t)n * DDIM))[t] = q;
}

__global__ void zero_lacc(float* lacc)
{
    if (threadIdx.x < 4) lacc[threadIdx.x] = 0.f;
}

__global__ void write_loss(const float* __restrict__ lacc, float* __restrict__ out)
{
    if (threadIdx.x == 0) {
        float total = lacc[0] + lacc[1] + lacc[2] + lacc[3];
        out[0] = 1.25f * total * (1.0f / ((float)NTOK * (float)DDIM));
    }
}

// ---------------- host ----------------
extern "C" void kernel_launch(void* const* d_in, const int* in_sizes, int n_in,
                              void* d_out, int out_size)
{
    const float* x   = (const float*)d_in[0];
    const float* tW  = (const float*)d_in[1];
    const float* tb  = (const float*)d_in[2];
    const float* eW  = (const float*)d_in[3];
    const float* eb  = (const float*)d_in[4];
    const float* dW  = (const float*)d_in[5];
    const float* db  = (const float*)d_in[6];
    const float* oW  = (const float*)d_in[7];
    const float* ob  = (const float*)d_in[8];
    const float* tcb = (const float*)d_in[9];
    const float* ecb = (const float*)d_in[10];
    const float* cb0 = (const float*)d_in[11];
    const float* cb1 = (const float*)d_in[12];

    float* out = (float*)d_out;
    float* q_out    = out;                               // [NTOK*DDIM]
    float* idxf     = out + (size_t)NTOK * DDIM;         // 4x [NTOK]
    float* loss_out = idxf + (size_t)4 * NTOK;           // [1]

    float *tfeat, *efeat, *dfeat, *resid, *rown, *E, *cn, *lacc;
    int* idx;
    cudaGetSymbolAddress((void**)&tfeat, g_tfeat);
    cudaGetSymbolAddress((void**)&efeat, g_efeat);
    cudaGetSymbolAddress((void**)&dfeat, g_dfeat);
    cudaGetSymbolAddress((void**)&resid, g_resid);
    cudaGetSymbolAddress((void**)&rown,  g_rown);
    cudaGetSymbolAddress((void**)&idx,   g_idx);
    cudaGetSymbolAddress((void**)&E,     g_E);
    cudaGetSymbolAddress((void**)&cn,    g_cn);
    cudaGetSymbolAddress((void**)&lacc,  g_lacc);

    // side stream for work independent of the feature GEMMs
    cudaStream_t s2;
    cudaStreamCreate(&s2);
    cudaEvent_t evFork, evJoin;
    cudaEventCreateWithFlags(&evFork, cudaEventDisableTiming);
    cudaEventCreateWithFlags(&evJoin, cudaEventDisableTiming);

    zero_lacc<<<1, 32>>>(lacc);

    // fork: codebook norms + E-projection run concurrently with feature GEMMs
    cudaEventRecord(evFork, 0);
    cudaStreamWaitEvent(s2, evFork, 0);
    cbnorm<<<KTOT, 128, 0, s2>>>(tcb, ecb, cb0, cb1, cn);
    eproj_gemm<<<dim3(DDIM / TBN, 14), 128, 0, s2>>>(tcb, ecb, cb0, cb1, oW, E);
    cudaEventRecord(evJoin, s2);

    // main stream: 3 feature linears (+ fused rownorm partials)
    dim3 gfeat(DDIM / TBN, NTOK / TBM, 3);
    feat3_gemm<<<gfeat, 128>>>(x, tW, tb, eW, eb, dW, db, tfeat, efeat, dfeat);
    combine_rown<<<3 * NTOK / 256, 256>>>();

    // join before anything that needs cn / E
    cudaStreamWaitEvent(0, evJoin, 0);

    // first 3 VQ stages fused (losses from d_min; detail stage emits |resid|^2)
    dim3 gvq(NTOK / TBM, 3);
    vq3<<<gvq, 128>>>(tfeat, efeat, dfeat, tcb, ecb, cb0, rown, cn,
                      idx, idxf, lacc, rown + 3 * NTOK);

    // residual for stage-2 detail
    make_resid<<<NTOK, 128>>>(dfeat, cb0, idx, resid);

    // second detail stage on residual (loss -> lacc[3])
    vq1<<<NTOK / TBM, 128>>>(resid, cb1, rown + 3 * NTOK,
                             cn + KT + KE + KD, KD,
                             idx + 3 * NTOK, idxf + 3 * NTOK, lacc + 3);

    // gather-add projected codebooks -> quantized output
    finalize_out<<<NTOK, 128>>>(E, ob, idx, q_out);

    write_loss<<<1, 32>>>(lacc, loss_out);

    cudaStreamDestroy(s2);
    cudaEventDestroy(evFork);
    cudaEventDestroy(evJoin);
}